// round 6
// baseline (speedup 1.0000x reference)
#include <cuda_runtime.h>
#include <cstdint>

#define NB 16
#define NN 8192
#define NDIM 384
#define NR 64
#define NG 128
#define NS 64
#define MT (NB*NN)   // 131072 rows

// ---------------- scratch (no allocations allowed) ----------------
__device__ __align__(256) float g_h[(size_t)MT*NR];   // 33.5 MB
__device__ __align__(256) float g_y[(size_t)MT*NR];   // 33.5 MB
__device__ __align__(256) int   g_idx[2*MT];          // normalized int32 indices
__device__ int g_is64;

__device__ __forceinline__ float silu_f(float x){ return x / (1.0f + __expf(-x)); }

__device__ __forceinline__ void fma4x4(float (&acc)[4][4], float4 a, float4 b){
    float av[4] = {a.x,a.y,a.z,a.w};
    float bv[4] = {b.x,b.y,b.z,b.w};
    #pragma unroll
    for (int i=0;i<4;i++)
        #pragma unroll
        for (int j=0;j<4;j++)
            acc[i][j] += av[i]*bv[j];
}

// ---------------- idx dtype probe + normalize ----------------
// Values are in [0, 8192). If the array is int64 (little-endian), every odd
// 32-bit word is 0. If int32, odd words are random nonzero indices
// (P[all 128 zero] ~ (1/8192)^128 ~ 0).
__global__ void probe_idx_kernel(const unsigned int* __restrict__ w){
    __shared__ int ok;
    if (threadIdx.x == 0) ok = 1;
    __syncthreads();
    if (w[2*threadIdx.x + 1] != 0u) ok = 0;   // benign race, all write 0
    __syncthreads();
    if (threadIdx.x == 0) g_is64 = ok;
}

__global__ void convert_idx_kernel(const void* __restrict__ p){
    int i = blockIdx.x*blockDim.x + threadIdx.x;
    if (i >= 2*MT) return;
    if (g_is64) g_idx[i] = (int)((const long long*)p)[i];
    else        g_idx[i] = ((const int*)p)[i];
}

// ---------------- K1: h = silu(X @ Wd^T + bd) ----------------
// C[131072,64] = A[131072,384] * Wd[64,384]^T. BM=64, BN=64, BK=32.
__global__ __launch_bounds__(256) void down_kernel(
    const float* __restrict__ A, const float* __restrict__ Wd,
    const float* __restrict__ bd)
{
    __shared__ float As[32][68];  // k-major: As[k][m]
    __shared__ float Bs[32][68];  // k-major: Bs[k][n] = Wd[n][k]
    const int tid = threadIdx.x;
    const int tx = tid & 15, ty = tid >> 4;
    const int m0 = blockIdx.x * 64;
    const int lr = tid >> 3;         // 0..31
    const int lk = (tid & 7) * 4;    // 0..28

    float acc[4][4] = {};
    for (int kk = 0; kk < NDIM; kk += 32){
        float4 a0 = *(const float4*)(A + (size_t)(m0+lr   )*NDIM + kk + lk);
        float4 a1 = *(const float4*)(A + (size_t)(m0+lr+32)*NDIM + kk + lk);
        float4 b0 = *(const float4*)(Wd + (size_t)(lr   )*NDIM + kk + lk);
        float4 b1 = *(const float4*)(Wd + (size_t)(lr+32)*NDIM + kk + lk);
        __syncthreads();
        As[lk+0][lr]=a0.x; As[lk+1][lr]=a0.y; As[lk+2][lr]=a0.z; As[lk+3][lr]=a0.w;
        As[lk+0][lr+32]=a1.x; As[lk+1][lr+32]=a1.y; As[lk+2][lr+32]=a1.z; As[lk+3][lr+32]=a1.w;
        Bs[lk+0][lr]=b0.x; Bs[lk+1][lr]=b0.y; Bs[lk+2][lr]=b0.z; Bs[lk+3][lr]=b0.w;
        Bs[lk+0][lr+32]=b1.x; Bs[lk+1][lr+32]=b1.y; Bs[lk+2][lr+32]=b1.z; Bs[lk+3][lr+32]=b1.w;
        __syncthreads();
        #pragma unroll
        for (int k = 0; k < 32; k++){
            float4 af = *(const float4*)&As[k][ty*4];
            float4 bf = *(const float4*)&Bs[k][tx*4];
            fma4x4(acc, af, bf);
        }
    }
    float4 bb = *(const float4*)(bd + tx*4);
    #pragma unroll
    for (int i=0;i<4;i++){
        float4 o;
        o.x = silu_f(acc[i][0] + bb.x);
        o.y = silu_f(acc[i][1] + bb.y);
        o.z = silu_f(acc[i][2] + bb.z);
        o.w = silu_f(acc[i][3] + bb.w);
        *(float4*)(g_h + (size_t)(m0+ty*4+i)*NR + tx*4) = o;
    }
}

// ---------------- K2: fused per-(b,g) branch (branch 1 only; branch 0 is dead)
//   X[t][r]  = h[b, idx0[b, g*64+t], r]          (gather fused into load)
//   F        = U^T @ X
//   F2       = F + silu(LN(F) @ Wa^T + ba)
//   Y        = U @ F2  -> g_y
#define K3_SMEM (5*64*68*4 + 3*64*4)
__global__ __launch_bounds__(256) void group_kernel(
    const float* __restrict__ subU, const float* __restrict__ Wa,
    const float* __restrict__ ba, const float* __restrict__ gamma,
    const float* __restrict__ beta)
{
    extern __shared__ float sm[];
    float* Ug  = sm;              // [64][68]  Ug[t][s]  = U[t][s] (as stored)
    float* Ut  = Ug  + 64*68;     // [64][68]  Ut[t][s]  = U[s][t] (transposed)
    float* Xs  = Ut  + 64*68;     // [64][68]  sub_x[t][r]; later LNT[k][s]
    float* Fs  = Xs  + 64*68;     // [64][68]  F[s][r]; later F2
    float* WaT = Fs  + 64*68;     // [64][68]  WaT[k][r] = Wa[r][k]
    float* sGa = WaT + 64*68;     // [64]
    float* sBe = sGa + 64;        // [64]
    float* sBa = sBe + 64;        // [64]

    const int tid = threadIdx.x;
    const int tx = tid & 15, ty = tid >> 4;
    const int bg = blockIdx.x;
    const int b = bg >> 7, g = bg & 127;
    const float* U = subU + ((size_t)(16 + b)*128 + g)*4096;  // sub_U[1][b][g]

    const int row = tid >> 2;        // 0..63
    const int c0  = (tid & 3) * 16;  // 0,16,32,48
    const int src = g_idx[b*NN + g*64 + row];                 // idx[0]
    const float* hsrc = g_h + ((size_t)b*NN + src)*NR;

    #pragma unroll
    for (int c = 0; c < 16; c += 4){
        float4 u = *(const float4*)(U + row*64 + c0 + c);
        *(float4*)&Ug[row*68 + c0 + c] = u;
        Ut[(c0+c+0)*68 + row] = u.x;
        Ut[(c0+c+1)*68 + row] = u.y;
        Ut[(c0+c+2)*68 + row] = u.z;
        Ut[(c0+c+3)*68 + row] = u.w;
        float4 w = *(const float4*)(Wa + row*64 + c0 + c);
        WaT[(c0+c+0)*68 + row] = w.x;
        WaT[(c0+c+1)*68 + row] = w.y;
        WaT[(c0+c+2)*68 + row] = w.z;
        WaT[(c0+c+3)*68 + row] = w.w;
        float4 x = *(const float4*)(hsrc + c0 + c);
        *(float4*)&Xs[row*68 + c0 + c] = x;
    }
    if (tid < 64){ sGa[tid]=gamma[tid]; sBe[tid]=beta[tid]; sBa[tid]=ba[tid]; }
    __syncthreads();

    // GEMM1: F[s][r] = sum_t U[t][s] * X[t][r]
    float accF[4][4] = {};
    #pragma unroll 8
    for (int t = 0; t < 64; t++){
        float4 af = *(const float4*)&Ug[t*68 + ty*4];
        float4 bf = *(const float4*)&Xs[t*68 + tx*4];
        fma4x4(accF, af, bf);
    }
    #pragma unroll
    for (int i=0;i<4;i++)
        *(float4*)&Fs[(ty*4+i)*68 + tx*4] =
            make_float4(accF[i][0],accF[i][1],accF[i][2],accF[i][3]);
    __syncthreads();

    // LayerNorm over r (64) for row s=row; ddof=0, eps=1e-5
    float ssum=0.f, ssq=0.f;
    #pragma unroll
    for (int c=0;c<16;c+=4){
        float4 f = *(const float4*)&Fs[row*68 + c0 + c];
        ssum += f.x+f.y+f.z+f.w;
        ssq  += f.x*f.x + f.y*f.y + f.z*f.z + f.w*f.w;
    }
    ssum += __shfl_xor_sync(0xffffffffu, ssum, 1);
    ssq  += __shfl_xor_sync(0xffffffffu, ssq , 1);
    ssum += __shfl_xor_sync(0xffffffffu, ssum, 2);
    ssq  += __shfl_xor_sync(0xffffffffu, ssq , 2);
    float mean = ssum * (1.0f/64.0f);
    float var  = ssq  * (1.0f/64.0f) - mean*mean;
    float rstd = rsqrtf(var + 1e-5f);
    // LNT[k][s] into Xs (transposed for GEMM2 A-side LDS.128)
    #pragma unroll
    for (int c=0;c<16;c+=4){
        float4 f = *(const float4*)&Fs[row*68 + c0 + c];
        Xs[(c0+c+0)*68 + row] = (f.x-mean)*rstd*sGa[c0+c+0] + sBe[c0+c+0];
        Xs[(c0+c+1)*68 + row] = (f.y-mean)*rstd*sGa[c0+c+1] + sBe[c0+c+1];
        Xs[(c0+c+2)*68 + row] = (f.z-mean)*rstd*sGa[c0+c+2] + sBe[c0+c+2];
        Xs[(c0+c+3)*68 + row] = (f.w-mean)*rstd*sGa[c0+c+3] + sBe[c0+c+3];
    }
    __syncthreads();

    // GEMM2: G[s][r] = sum_k LN(F)[s][k] * Wa[r][k];  F2 = F + silu(G + ba)
    float accG[4][4] = {};
    #pragma unroll 8
    for (int t = 0; t < 64; t++){
        float4 af = *(const float4*)&Xs[t*68 + ty*4];
        float4 bf = *(const float4*)&WaT[t*68 + tx*4];
        fma4x4(accG, af, bf);
    }
    #pragma unroll
    for (int i=0;i<4;i++){
        float4 o;
        o.x = accF[i][0] + silu_f(accG[i][0] + sBa[tx*4+0]);
        o.y = accF[i][1] + silu_f(accG[i][1] + sBa[tx*4+1]);
        o.z = accF[i][2] + silu_f(accG[i][2] + sBa[tx*4+2]);
        o.w = accF[i][3] + silu_f(accG[i][3] + sBa[tx*4+3]);
        *(float4*)&Fs[(ty*4+i)*68 + tx*4] = o;
    }
    __syncthreads();

    // GEMM3: Y[s][r] = sum_t U[s][t] * F2[t][r]
    float accY[4][4] = {};
    #pragma unroll 8
    for (int t = 0; t < 64; t++){
        float4 af = *(const float4*)&Ut[t*68 + ty*4];
        float4 bf = *(const float4*)&Fs[t*68 + tx*4];
        fma4x4(accY, af, bf);
    }
    float* yout = g_y + ((size_t)b*NN + g*64)*NR;
    #pragma unroll
    for (int i=0;i<4;i++)
        *(float4*)(yout + (size_t)(ty*4+i)*NR + tx*4) =
            make_float4(accY[i][0],accY[i][1],accY[i][2],accY[i][3]);
}

// ---------------- K3: h <- h + y + gather(y, idx[1])  (in-place, per-element RMW)
__global__ void combine_kernel(){
    int gid = blockIdx.x*blockDim.x + threadIdx.x;   // one float4 each
    if (gid >= MT*NR/4) return;
    int rowi = gid >> 4;          // row 0..131071
    int q    = (gid & 15) * 4;    // col offset
    int b = rowi >> 13, j = rowi & (NN-1);
    int src = g_idx[MT + b*NN + j];                   // idx[1]
    float4 yg = *(const float4*)(g_y + ((size_t)b*NN + src)*NR + q);
    float4 yd = *(const float4*)(g_y + (size_t)rowi*NR + q);
    float4 hh = *(const float4*)(g_h + (size_t)rowi*NR + q);
    hh.x += yg.x + yd.x;  hh.y += yg.y + yd.y;
    hh.z += yg.z + yd.z;  hh.w += yg.w + yd.w;
    *(float4*)(g_h + (size_t)rowi*NR + q) = hh;
}

// ---------------- K4: out = h @ Wu^T + bu ----------------
// out[131072,384] = h[131072,64] * Wu[384,64]^T. BM=64, BN=128, single K pass.
#define K4_SMEM (64*68*4 + 64*132*4 + 128*4)
__global__ __launch_bounds__(256) void up_kernel(
    const float* __restrict__ Wu, const float* __restrict__ bu,
    float* __restrict__ out)
{
    extern __shared__ float sm[];
    float* Hs  = sm;            // [64][68]   Hs[k][m]
    float* Ws  = Hs + 64*68;    // [64][132]  Ws[k][n] = Wu[n0+n][k]
    float* sBu = Ws + 64*132;   // [128]
    const int tid = threadIdx.x;
    const int tx = tid & 15, ty = tid >> 4;
    const int m0 = blockIdx.x * 64;
    const int n0 = blockIdx.y * 128;
    {
        int row = tid >> 2, c0 = (tid & 3)*16;
        const float* src = g_h + (size_t)(m0+row)*NR;
        #pragma unroll
        for (int c=0;c<16;c+=4){
            float4 v = *(const float4*)(src + c0 + c);
            Hs[(c0+c+0)*68 + row] = v.x;
            Hs[(c0+c+1)*68 + row] = v.y;
            Hs[(c0+c+2)*68 + row] = v.z;
            Hs[(c0+c+3)*68 + row] = v.w;
        }
        int nloc = tid >> 1, half = (tid & 1)*32;
        const float* wsrc = Wu + (size_t)(n0+nloc)*NR + half;
        #pragma unroll
        for (int c=0;c<32;c+=4){
            float4 w = *(const float4*)(wsrc + c);
            Ws[(half+c+0)*132 + nloc] = w.x;
            Ws[(half+c+1)*132 + nloc] = w.y;
            Ws[(half+c+2)*132 + nloc] = w.z;
            Ws[(half+c+3)*132 + nloc] = w.w;
        }
        if (tid < 128) sBu[tid] = bu[n0 + tid];
    }
    __syncthreads();

    float acc[4][8] = {};
    #pragma unroll 8
    for (int k=0;k<64;k++){
        float4 af = *(const float4*)&Hs[k*68 + ty*4];
        float4 b0 = *(const float4*)&Ws[k*132 + tx*8];
        float4 b1 = *(const float4*)&Ws[k*132 + tx*8 + 4];
        float av[4]={af.x,af.y,af.z,af.w};
        float bv[8]={b0.x,b0.y,b0.z,b0.w,b1.x,b1.y,b1.z,b1.w};
        #pragma unroll
        for (int i=0;i<4;i++)
            #pragma unroll
            for (int j=0;j<8;j++)
                acc[i][j] += av[i]*bv[j];
    }
    #pragma unroll
    for (int i=0;i<4;i++){
        float4 o0, o1;
        o0.x = acc[i][0] + sBu[tx*8+0];
        o0.y = acc[i][1] + sBu[tx*8+1];
        o0.z = acc[i][2] + sBu[tx*8+2];
        o0.w = acc[i][3] + sBu[tx*8+3];
        o1.x = acc[i][4] + sBu[tx*8+4];
        o1.y = acc[i][5] + sBu[tx*8+5];
        o1.z = acc[i][6] + sBu[tx*8+6];
        o1.w = acc[i][7] + sBu[tx*8+7];
        float* dst = out + (size_t)(m0+ty*4+i)*NDIM + n0 + tx*8;
        *(float4*)dst       = o0;
        *(float4*)(dst + 4) = o1;
    }
}

// ---------------- launch ----------------
extern "C" void kernel_launch(void* const* d_in, const int* in_sizes, int n_in,
                              void* d_out, int out_size)
{
    const float* input = (const float*)d_in[0];
    const float* subU  = (const float*)d_in[1];
    const void*  idx   = d_in[2];
    const float* Wd    = (const float*)d_in[3];
    const float* bd    = (const float*)d_in[4];
    const float* Wu    = (const float*)d_in[5];
    const float* bu    = (const float*)d_in[6];
    const float* Wa    = (const float*)d_in[7];
    const float* ba    = (const float*)d_in[8];
    const float* ga    = (const float*)d_in[9];
    const float* be    = (const float*)d_in[10];
    float* out = (float*)d_out;
    (void)in_sizes; (void)n_in; (void)out_size;

    cudaFuncSetAttribute(group_kernel, cudaFuncAttributeMaxDynamicSharedMemorySize, K3_SMEM);
    cudaFuncSetAttribute(up_kernel,    cudaFuncAttributeMaxDynamicSharedMemorySize, K4_SMEM);

    probe_idx_kernel<<<1, 128>>>((const unsigned int*)idx);
    convert_idx_kernel<<<(2*MT + 255)/256, 256>>>(idx);
    down_kernel<<<MT/64, 256>>>(input, Wd, bd);
    group_kernel<<<NB*NG, 256, K3_SMEM>>>(subU, Wa, ba, ga, be);
    combine_kernel<<<(MT*NR/4 + 255)/256, 256>>>();
    up_kernel<<<dim3(MT/64, 3), 256, K4_SMEM>>>(Wu, bu, out);
}

// round 7
// speedup vs baseline: 1.0008x; 1.0008x over previous
#include <cuda_runtime.h>
#include <cstdint>

#define NB 16
#define NN 8192
#define NDIM 384
#define NR 64
#define NG 128
#define NS 64
#define MT (NB*NN)   // 131072 rows

// ---------------- scratch (no allocations allowed) ----------------
__device__ __align__(256) float g_h[(size_t)MT*NR];   // 33.5 MB
__device__ __align__(256) float g_y[(size_t)MT*NR];   // 33.5 MB
__device__ __align__(256) int   g_idx[2*MT];          // normalized int32 indices
__device__ int g_is64;

__device__ __forceinline__ float silu_f(float x){ return x / (1.0f + __expf(-x)); }

__device__ __forceinline__ void fma4x4(float (&acc)[4][4], float4 a, float4 b){
    float av[4] = {a.x,a.y,a.z,a.w};
    float bv[4] = {b.x,b.y,b.z,b.w};
    #pragma unroll
    for (int i=0;i<4;i++)
        #pragma unroll
        for (int j=0;j<4;j++)
            acc[i][j] += av[i]*bv[j];
}

// ---------------- idx dtype probe + normalize ----------------
// Values are in [0, 8192). If the array is int64 (little-endian), every odd
// 32-bit word is 0. If int32, odd words are random nonzero indices
// (P[all 128 zero] ~ (1/8192)^128 ~ 0).
__global__ void probe_idx_kernel(const unsigned int* __restrict__ w){
    __shared__ int ok;
    if (threadIdx.x == 0) ok = 1;
    __syncthreads();
    if (w[2*threadIdx.x + 1] != 0u) ok = 0;   // benign race, all write 0
    __syncthreads();
    if (threadIdx.x == 0) g_is64 = ok;
}

__global__ void convert_idx_kernel(const void* __restrict__ p){
    int i = blockIdx.x*blockDim.x + threadIdx.x;
    if (i >= 2*MT) return;
    if (g_is64) g_idx[i] = (int)((const long long*)p)[i];
    else        g_idx[i] = ((const int*)p)[i];
}

// ---------------- K1: h = silu(X @ Wd^T + bd) ----------------
// C[131072,64] = A[131072,384] * Wd[64,384]^T. BM=64, BN=64, BK=32.
__global__ __launch_bounds__(256) void down_kernel(
    const float* __restrict__ A, const float* __restrict__ Wd,
    const float* __restrict__ bd)
{
    __shared__ float As[32][68];  // k-major: As[k][m]
    __shared__ float Bs[32][68];  // k-major: Bs[k][n] = Wd[n][k]
    const int tid = threadIdx.x;
    const int tx = tid & 15, ty = tid >> 4;
    const int m0 = blockIdx.x * 64;
    const int lr = tid >> 3;         // 0..31
    const int lk = (tid & 7) * 4;    // 0..28

    float acc[4][4] = {};
    for (int kk = 0; kk < NDIM; kk += 32){
        float4 a0 = *(const float4*)(A + (size_t)(m0+lr   )*NDIM + kk + lk);
        float4 a1 = *(const float4*)(A + (size_t)(m0+lr+32)*NDIM + kk + lk);
        float4 b0 = *(const float4*)(Wd + (size_t)(lr   )*NDIM + kk + lk);
        float4 b1 = *(const float4*)(Wd + (size_t)(lr+32)*NDIM + kk + lk);
        __syncthreads();
        As[lk+0][lr]=a0.x; As[lk+1][lr]=a0.y; As[lk+2][lr]=a0.z; As[lk+3][lr]=a0.w;
        As[lk+0][lr+32]=a1.x; As[lk+1][lr+32]=a1.y; As[lk+2][lr+32]=a1.z; As[lk+3][lr+32]=a1.w;
        Bs[lk+0][lr]=b0.x; Bs[lk+1][lr]=b0.y; Bs[lk+2][lr]=b0.z; Bs[lk+3][lr]=b0.w;
        Bs[lk+0][lr+32]=b1.x; Bs[lk+1][lr+32]=b1.y; Bs[lk+2][lr+32]=b1.z; Bs[lk+3][lr+32]=b1.w;
        __syncthreads();
        #pragma unroll
        for (int k = 0; k < 32; k++){
            float4 af = *(const float4*)&As[k][ty*4];
            float4 bf = *(const float4*)&Bs[k][tx*4];
            fma4x4(acc, af, bf);
        }
    }
    float4 bb = *(const float4*)(bd + tx*4);
    #pragma unroll
    for (int i=0;i<4;i++){
        float4 o;
        o.x = silu_f(acc[i][0] + bb.x);
        o.y = silu_f(acc[i][1] + bb.y);
        o.z = silu_f(acc[i][2] + bb.z);
        o.w = silu_f(acc[i][3] + bb.w);
        *(float4*)(g_h + (size_t)(m0+ty*4+i)*NR + tx*4) = o;
    }
}

// ---------------- K2: fused per-(b,g) branch (branch 1 only; branch 0 is dead)
//   X[t][r]  = h[b, idx0[b, g*64+t], r]          (gather fused into load)
//   F        = U^T @ X
//   F2       = F + silu(LN(F) @ Wa^T + ba)
//   Y        = U @ F2  -> g_y
#define K3_SMEM (5*64*68*4 + 3*64*4)
__global__ __launch_bounds__(256) void group_kernel(
    const float* __restrict__ subU, const float* __restrict__ Wa,
    const float* __restrict__ ba, const float* __restrict__ gamma,
    const float* __restrict__ beta)
{
    extern __shared__ float sm[];
    float* Ug  = sm;              // [64][68]  Ug[t][s]  = U[t][s] (as stored)
    float* Ut  = Ug  + 64*68;     // [64][68]  Ut[t][s]  = U[s][t] (transposed)
    float* Xs  = Ut  + 64*68;     // [64][68]  sub_x[t][r]; later LNT[k][s]
    float* Fs  = Xs  + 64*68;     // [64][68]  F[s][r]; later F2
    float* WaT = Fs  + 64*68;     // [64][68]  WaT[k][r] = Wa[r][k]
    float* sGa = WaT + 64*68;     // [64]
    float* sBe = sGa + 64;        // [64]
    float* sBa = sBe + 64;        // [64]

    const int tid = threadIdx.x;
    const int tx = tid & 15, ty = tid >> 4;
    const int bg = blockIdx.x;
    const int b = bg >> 7, g = bg & 127;
    const float* U = subU + ((size_t)(16 + b)*128 + g)*4096;  // sub_U[1][b][g]

    const int row = tid >> 2;        // 0..63
    const int c0  = (tid & 3) * 16;  // 0,16,32,48
    const int src = g_idx[b*NN + g*64 + row];                 // idx[0]
    const float* hsrc = g_h + ((size_t)b*NN + src)*NR;

    #pragma unroll
    for (int c = 0; c < 16; c += 4){
        float4 u = *(const float4*)(U + row*64 + c0 + c);
        *(float4*)&Ug[row*68 + c0 + c] = u;
        Ut[(c0+c+0)*68 + row] = u.x;
        Ut[(c0+c+1)*68 + row] = u.y;
        Ut[(c0+c+2)*68 + row] = u.z;
        Ut[(c0+c+3)*68 + row] = u.w;
        float4 w = *(const float4*)(Wa + row*64 + c0 + c);
        WaT[(c0+c+0)*68 + row] = w.x;
        WaT[(c0+c+1)*68 + row] = w.y;
        WaT[(c0+c+2)*68 + row] = w.z;
        WaT[(c0+c+3)*68 + row] = w.w;
        float4 x = *(const float4*)(hsrc + c0 + c);
        *(float4*)&Xs[row*68 + c0 + c] = x;
    }
    if (tid < 64){ sGa[tid]=gamma[tid]; sBe[tid]=beta[tid]; sBa[tid]=ba[tid]; }
    __syncthreads();

    // GEMM1: F[s][r] = sum_t U[t][s] * X[t][r]
    float accF[4][4] = {};
    #pragma unroll 8
    for (int t = 0; t < 64; t++){
        float4 af = *(const float4*)&Ug[t*68 + ty*4];
        float4 bf = *(const float4*)&Xs[t*68 + tx*4];
        fma4x4(accF, af, bf);
    }
    #pragma unroll
    for (int i=0;i<4;i++)
        *(float4*)&Fs[(ty*4+i)*68 + tx*4] =
            make_float4(accF[i][0],accF[i][1],accF[i][2],accF[i][3]);
    __syncthreads();

    // LayerNorm over r (64) for row s=row; ddof=0, eps=1e-5
    float ssum=0.f, ssq=0.f;
    #pragma unroll
    for (int c=0;c<16;c+=4){
        float4 f = *(const float4*)&Fs[row*68 + c0 + c];
        ssum += f.x+f.y+f.z+f.w;
        ssq  += f.x*f.x + f.y*f.y + f.z*f.z + f.w*f.w;
    }
    ssum += __shfl_xor_sync(0xffffffffu, ssum, 1);
    ssq  += __shfl_xor_sync(0xffffffffu, ssq , 1);
    ssum += __shfl_xor_sync(0xffffffffu, ssum, 2);
    ssq  += __shfl_xor_sync(0xffffffffu, ssq , 2);
    float mean = ssum * (1.0f/64.0f);
    float var  = ssq  * (1.0f/64.0f) - mean*mean;
    float rstd = rsqrtf(var + 1e-5f);
    // LNT[k][s] into Xs (transposed for GEMM2 A-side LDS.128)
    #pragma unroll
    for (int c=0;c<16;c+=4){
        float4 f = *(const float4*)&Fs[row*68 + c0 + c];
        Xs[(c0+c+0)*68 + row] = (f.x-mean)*rstd*sGa[c0+c+0] + sBe[c0+c+0];
        Xs[(c0+c+1)*68 + row] = (f.y-mean)*rstd*sGa[c0+c+1] + sBe[c0+c+1];
        Xs[(c0+c+2)*68 + row] = (f.z-mean)*rstd*sGa[c0+c+2] + sBe[c0+c+2];
        Xs[(c0+c+3)*68 + row] = (f.w-mean)*rstd*sGa[c0+c+3] + sBe[c0+c+3];
    }
    __syncthreads();

    // GEMM2: G[s][r] = sum_k LN(F)[s][k] * Wa[r][k];  F2 = F + silu(G + ba)
    float accG[4][4] = {};
    #pragma unroll 8
    for (int t = 0; t < 64; t++){
        float4 af = *(const float4*)&Xs[t*68 + ty*4];
        float4 bf = *(const float4*)&WaT[t*68 + tx*4];
        fma4x4(accG, af, bf);
    }
    #pragma unroll
    for (int i=0;i<4;i++){
        float4 o;
        o.x = accF[i][0] + silu_f(accG[i][0] + sBa[tx*4+0]);
        o.y = accF[i][1] + silu_f(accG[i][1] + sBa[tx*4+1]);
        o.z = accF[i][2] + silu_f(accG[i][2] + sBa[tx*4+2]);
        o.w = accF[i][3] + silu_f(accG[i][3] + sBa[tx*4+3]);
        *(float4*)&Fs[(ty*4+i)*68 + tx*4] = o;
    }
    __syncthreads();

    // GEMM3: Y[s][r] = sum_t U[s][t] * F2[t][r]
    float accY[4][4] = {};
    #pragma unroll 8
    for (int t = 0; t < 64; t++){
        float4 af = *(const float4*)&Ut[t*68 + ty*4];
        float4 bf = *(const float4*)&Fs[t*68 + tx*4];
        fma4x4(accY, af, bf);
    }
    float* yout = g_y + ((size_t)b*NN + g*64)*NR;
    #pragma unroll
    for (int i=0;i<4;i++)
        *(float4*)(yout + (size_t)(ty*4+i)*NR + tx*4) =
            make_float4(accY[i][0],accY[i][1],accY[i][2],accY[i][3]);
}

// ---------------- K3: h <- h + y + gather(y, idx[1])  (in-place, per-element RMW)
__global__ void combine_kernel(){
    int gid = blockIdx.x*blockDim.x + threadIdx.x;   // one float4 each
    if (gid >= MT*NR/4) return;
    int rowi = gid >> 4;          // row 0..131071
    int q    = (gid & 15) * 4;    // col offset
    int b = rowi >> 13, j = rowi & (NN-1);
    int src = g_idx[MT + b*NN + j];                   // idx[1]
    float4 yg = *(const float4*)(g_y + ((size_t)b*NN + src)*NR + q);
    float4 yd = *(const float4*)(g_y + (size_t)rowi*NR + q);
    float4 hh = *(const float4*)(g_h + (size_t)rowi*NR + q);
    hh.x += yg.x + yd.x;  hh.y += yg.y + yd.y;
    hh.z += yg.z + yd.z;  hh.w += yg.w + yd.w;
    *(float4*)(g_h + (size_t)rowi*NR + q) = hh;
}

// ---------------- K4: out = h @ Wu^T + bu ----------------
// out[131072,384] = h[131072,64] * Wu[384,64]^T. BM=64, BN=128, single K pass.
#define K4_SMEM (64*68*4 + 64*132*4 + 128*4)
__global__ __launch_bounds__(256) void up_kernel(
    const float* __restrict__ Wu, const float* __restrict__ bu,
    float* __restrict__ out)
{
    extern __shared__ float sm[];
    float* Hs  = sm;            // [64][68]   Hs[k][m]
    float* Ws  = Hs + 64*68;    // [64][132]  Ws[k][n] = Wu[n0+n][k]
    float* sBu = Ws + 64*132;   // [128]
    const int tid = threadIdx.x;
    const int tx = tid & 15, ty = tid >> 4;
    const int m0 = blockIdx.x * 64;
    const int n0 = blockIdx.y * 128;
    {
        int row = tid >> 2, c0 = (tid & 3)*16;
        const float* src = g_h + (size_t)(m0+row)*NR;
        #pragma unroll
        for (int c=0;c<16;c+=4){
            float4 v = *(const float4*)(src + c0 + c);
            Hs[(c0+c+0)*68 + row] = v.x;
            Hs[(c0+c+1)*68 + row] = v.y;
            Hs[(c0+c+2)*68 + row] = v.z;
            Hs[(c0+c+3)*68 + row] = v.w;
        }
        int nloc = tid >> 1, half = (tid & 1)*32;
        const float* wsrc = Wu + (size_t)(n0+nloc)*NR + half;
        #pragma unroll
        for (int c=0;c<32;c+=4){
            float4 w = *(const float4*)(wsrc + c);
            Ws[(half+c+0)*132 + nloc] = w.x;
            Ws[(half+c+1)*132 + nloc] = w.y;
            Ws[(half+c+2)*132 + nloc] = w.z;
            Ws[(half+c+3)*132 + nloc] = w.w;
        }
        if (tid < 128) sBu[tid] = bu[n0 + tid];
    }
    __syncthreads();

    float acc[4][8] = {};
    #pragma unroll 8
    for (int k=0;k<64;k++){
        float4 af = *(const float4*)&Hs[k*68 + ty*4];
        float4 b0 = *(const float4*)&Ws[k*132 + tx*8];
        float4 b1 = *(const float4*)&Ws[k*132 + tx*8 + 4];
        float av[4]={af.x,af.y,af.z,af.w};
        float bv[8]={b0.x,b0.y,b0.z,b0.w,b1.x,b1.y,b1.z,b1.w};
        #pragma unroll
        for (int i=0;i<4;i++)
            #pragma unroll
            for (int j=0;j<8;j++)
                acc[i][j] += av[i]*bv[j];
    }
    #pragma unroll
    for (int i=0;i<4;i++){
        float4 o0, o1;
        o0.x = acc[i][0] + sBu[tx*8+0];
        o0.y = acc[i][1] + sBu[tx*8+1];
        o0.z = acc[i][2] + sBu[tx*8+2];
        o0.w = acc[i][3] + sBu[tx*8+3];
        o1.x = acc[i][4] + sBu[tx*8+4];
        o1.y = acc[i][5] + sBu[tx*8+5];
        o1.z = acc[i][6] + sBu[tx*8+6];
        o1.w = acc[i][7] + sBu[tx*8+7];
        float* dst = out + (size_t)(m0+ty*4+i)*NDIM + n0 + tx*8;
        *(float4*)dst       = o0;
        *(float4*)(dst + 4) = o1;
    }
}

// ---------------- launch ----------------
extern "C" void kernel_launch(void* const* d_in, const int* in_sizes, int n_in,
                              void* d_out, int out_size)
{
    const float* input = (const float*)d_in[0];
    const float* subU  = (const float*)d_in[1];
    const void*  idx   = d_in[2];
    const float* Wd    = (const float*)d_in[3];
    const float* bd    = (const float*)d_in[4];
    const float* Wu    = (const float*)d_in[5];
    const float* bu    = (const float*)d_in[6];
    const float* Wa    = (const float*)d_in[7];
    const float* ba    = (const float*)d_in[8];
    const float* ga    = (const float*)d_in[9];
    const float* be    = (const float*)d_in[10];
    float* out = (float*)d_out;
    (void)in_sizes; (void)n_in; (void)out_size;

    cudaFuncSetAttribute(group_kernel, cudaFuncAttributeMaxDynamicSharedMemorySize, K3_SMEM);
    cudaFuncSetAttribute(up_kernel,    cudaFuncAttributeMaxDynamicSharedMemorySize, K4_SMEM);

    probe_idx_kernel<<<1, 128>>>((const unsigned int*)idx);
    convert_idx_kernel<<<(2*MT + 255)/256, 256>>>(idx);
    down_kernel<<<MT/64, 256>>>(input, Wd, bd);
    group_kernel<<<NB*NG, 256, K3_SMEM>>>(subU, Wa, ba, ga, be);
    combine_kernel<<<(MT*NR/4 + 255)/256, 256>>>();
    up_kernel<<<dim3(MT/64, 3), 256, K4_SMEM>>>(Wu, bu, out);
}